// round 7
// baseline (speedup 1.0000x reference)
#include <cuda_runtime.h>

#define NN 100000
#define NE 3200000
#define DD 64
#define EPSBN 1e-5f
#define CHUNK 512
#define NCHUNK ((NN + CHUNK - 1) / CHUNK)   // 196
#define BNODES 32                            // nodes per fused block
#define XSTR 36                              // Xt row stride (32 + pad 4)

// ---------------- scratch (no allocations allowed) ----------------
__device__ int   g_deg[NN];
__device__ int   g_off[NN + 1];
__device__ int   g_cursor[NN];
__device__ int   g_csum[256];
__device__ int   g_coff[256];
__device__ float g_dinv[NN];
__device__ int2  g_entries[NE];           // {src, weight-bits}
__device__ float g_y1[(size_t)NN * DD];
__device__ float g_y2[(size_t)NN * DD];
__device__ float g_stats[2 * DD];
__device__ float g_bn[2 * DD];
__device__ float g_wc[DD * DD];           // combined W@fw
__device__ float g_bc[DD];                // combined bias

// ---------------- CSR build ----------------
__global__ void k_zero_deg() {
    int i = blockIdx.x * blockDim.x + threadIdx.x;
    if (i < NN) g_deg[i] = 0;
}
__global__ void k_hist(const int* __restrict__ dst) {
    int e = blockIdx.x * blockDim.x + threadIdx.x;
    if (e < NE) atomicAdd(&g_deg[dst[e]], 1);
}
__global__ void k_scan1() {
    __shared__ int sh[CHUNK];
    int c = blockIdx.x, t = threadIdx.x;
    int i = c * CHUNK + t;
    int val = (i < NN) ? g_deg[i] : 0;
    sh[t] = val;
    __syncthreads();
    #pragma unroll
    for (int o = 1; o < CHUNK; o <<= 1) {
        int x = (t >= o) ? sh[t - o] : 0;
        __syncthreads();
        sh[t] += x;
        __syncthreads();
    }
    if (i < NN) g_off[i] = sh[t] - val;
    if (t == CHUNK - 1) g_csum[c] = sh[t];
}
__global__ void k_scan2() {
    __shared__ int sh[256];
    int t = threadIdx.x;
    int val = (t < NCHUNK) ? g_csum[t] : 0;
    sh[t] = val;
    __syncthreads();
    #pragma unroll
    for (int o = 1; o < 256; o <<= 1) {
        int x = (t >= o) ? sh[t - o] : 0;
        __syncthreads();
        sh[t] += x;
        __syncthreads();
    }
    g_coff[t] = sh[t] - val;
}
__global__ void k_scan3() {
    int i = blockIdx.x * blockDim.x + threadIdx.x;
    if (i < NN) {
        int v = g_off[i] + g_coff[i / CHUNK];
        g_off[i] = v;
        g_cursor[i] = v;
        g_dinv[i] = rsqrtf((float)(g_deg[i] + 1));   // +1 self loop
        if (i == 0) g_off[NN] = NE;
    }
}
__global__ void k_scatter(const int* __restrict__ src, const int* __restrict__ dst) {
    int e = blockIdx.x * blockDim.x + threadIdx.x;
    if (e >= NE) return;
    int s = src[e], d = dst[e];
    float w = g_dinv[s] * g_dinv[d];
    int pos = atomicAdd(&g_cursor[d], 1);
    g_entries[pos] = make_int2(s, __float_as_int(w));
}

// ---------------- weight combine: Wc = W@fw, bc = b@fw + fb; zero stats ---
__global__ void k_combine(const float* __restrict__ W, const float* __restrict__ fw,
                          const float* __restrict__ b, const float* __restrict__ fb) {
    int col = threadIdx.x;          // 0..63
    int rb  = threadIdx.y * 4;      // row base, y in 0..15
    float acc[4] = {0.f, 0.f, 0.f, 0.f};
    for (int k = 0; k < DD; k++) {
        float f = fw[k * DD + col];
        #pragma unroll
        for (int r = 0; r < 4; r++) acc[r] += W[(rb + r) * DD + k] * f;
    }
    #pragma unroll
    for (int r = 0; r < 4; r++) g_wc[(rb + r) * DD + col] = acc[r];
    if (threadIdx.y == 0) {
        float s = fb[col];
        for (int k = 0; k < DD; k++) s += b[k] * fw[k * DD + col];
        g_bc[col] = s;
    }
    if (threadIdx.y == 1) {
        g_stats[col] = 0.f;
        g_stats[64 + col] = 0.f;
    }
}

// ---------------- fused agg + GEMM --------------------------------------
// Phase A: 32 nodes/block, 16 threads/node gather Â·f(h) rows into smem Xt.
//   mode 0: raw rows; mode 2: relu(row*g_bn + g_bn[64..]) applied per load.
// Phase B: same 512 threads compute Xt^T-tile @ Wc + bc -> y, plus col stats.
__global__ void __launch_bounds__(512) k_agg_gemm(const float* __restrict__ h,
                                                  float* __restrict__ y,
                                                  int mode) {
    __shared__ float Xt[DD * XSTR];           // [k][node], stride 36
    __shared__ float Ws[DD * DD];
    __shared__ float sred[2][8][DD];

    const int tid = threadIdx.x;
    const int n0  = blockIdx.x * BNODES;

    // load Wc early (overlaps with gather latency)
    {
        int fi = tid * 8;                      // 512 threads * 8 floats = 4096
        *reinterpret_cast<float4*>(&Ws[fi]) =
            *reinterpret_cast<const float4*>(&g_wc[fi]);
        *reinterpret_cast<float4*>(&Ws[fi + 4]) =
            *reinterpret_cast<const float4*>(&g_wc[fi + 4]);
    }

    // ---- Phase A: aggregation ----
    {
        int ln   = tid >> 4;                   // 0..31 local node
        int q    = tid & 15;
        int node = n0 + ln;

        float4 sc = make_float4(1.f, 1.f, 1.f, 1.f);
        float4 sh = make_float4(0.f, 0.f, 0.f, 0.f);
        if (mode == 2) {
            sc = *reinterpret_cast<const float4*>(&g_bn[q * 4]);
            sh = *reinterpret_cast<const float4*>(&g_bn[64 + q * 4]);
        }

        float4 acc = make_float4(0.f, 0.f, 0.f, 0.f);
        if (node < NN) {
            int beg = g_off[node];
            int end = g_off[node + 1];
            float di = g_dinv[node];
            float ww = di * di;

            float4 a = *reinterpret_cast<const float4*>(h + (size_t)node * DD + q * 4);
            if (mode == 2) {
                a.x = fmaxf(a.x * sc.x + sh.x, 0.f);
                a.y = fmaxf(a.y * sc.y + sh.y, 0.f);
                a.z = fmaxf(a.z * sc.z + sh.z, 0.f);
                a.w = fmaxf(a.w * sc.w + sh.w, 0.f);
            }
            acc = make_float4(ww * a.x, ww * a.y, ww * a.z, ww * a.w);

            int e = beg;
            for (; e + 2 <= end; e += 2) {
                int2 e0 = g_entries[e];
                int2 e1 = g_entries[e + 1];
                float w0 = __int_as_float(e0.y);
                float w1 = __int_as_float(e1.y);
                float4 v0 = *reinterpret_cast<const float4*>(h + (size_t)e0.x * DD + q * 4);
                float4 v1 = *reinterpret_cast<const float4*>(h + (size_t)e1.x * DD + q * 4);
                if (mode == 2) {
                    v0.x = fmaxf(v0.x * sc.x + sh.x, 0.f);
                    v0.y = fmaxf(v0.y * sc.y + sh.y, 0.f);
                    v0.z = fmaxf(v0.z * sc.z + sh.z, 0.f);
                    v0.w = fmaxf(v0.w * sc.w + sh.w, 0.f);
                    v1.x = fmaxf(v1.x * sc.x + sh.x, 0.f);
                    v1.y = fmaxf(v1.y * sc.y + sh.y, 0.f);
                    v1.z = fmaxf(v1.z * sc.z + sh.z, 0.f);
                    v1.w = fmaxf(v1.w * sc.w + sh.w, 0.f);
                }
                acc.x += w0 * v0.x + w1 * v1.x;
                acc.y += w0 * v0.y + w1 * v1.y;
                acc.z += w0 * v0.z + w1 * v1.z;
                acc.w += w0 * v0.w + w1 * v1.w;
            }
            if (e < end) {
                int2 e0 = g_entries[e];
                float w0 = __int_as_float(e0.y);
                float4 v0 = *reinterpret_cast<const float4*>(h + (size_t)e0.x * DD + q * 4);
                if (mode == 2) {
                    v0.x = fmaxf(v0.x * sc.x + sh.x, 0.f);
                    v0.y = fmaxf(v0.y * sc.y + sh.y, 0.f);
                    v0.z = fmaxf(v0.z * sc.z + sh.z, 0.f);
                    v0.w = fmaxf(v0.w * sc.w + sh.w, 0.f);
                }
                acc.x += w0 * v0.x;
                acc.y += w0 * v0.y;
                acc.z += w0 * v0.z;
                acc.w += w0 * v0.w;
            }
        }
        int c0 = q * 4;
        Xt[(c0 + 0) * XSTR + ln] = acc.x;
        Xt[(c0 + 1) * XSTR + ln] = acc.y;
        Xt[(c0 + 2) * XSTR + ln] = acc.z;
        Xt[(c0 + 3) * XSTR + ln] = acc.w;
    }
    __syncthreads();

    // ---- Phase B: GEMM 32x64 @ 64x64, FFMA2 inner loop ----
    {
        const int col = tid & 63;              // output column
        const int rg  = tid >> 6;              // 0..7, rows rb..rb+3
        const int rb  = rg * 4;

        unsigned long long accp[2] = {0ull, 0ull};
        #pragma unroll 4
        for (int k = 0; k < DD; k++) {
            unsigned int wu = __float_as_uint(Ws[k * DD + col]);
            unsigned long long wp;
            asm("mov.b64 %0, {%1, %1};" : "=l"(wp) : "r"(wu));
            const ulonglong2* xp =
                reinterpret_cast<const ulonglong2*>(&Xt[k * XSTR + rb]);
            ulonglong2 a = *xp;
            asm("fma.rn.f32x2 %0, %1, %2, %0;" : "+l"(accp[0]) : "l"(a.x), "l"(wp));
            asm("fma.rn.f32x2 %0, %1, %2, %0;" : "+l"(accp[1]) : "l"(a.y), "l"(wp));
        }

        float ob = g_bc[col];
        float ps = 0.f, pss = 0.f;
        #pragma unroll
        for (int pr = 0; pr < 2; pr++) {
            unsigned int lo, hi;
            asm("mov.b64 {%0, %1}, %2;" : "=r"(lo), "=r"(hi) : "l"(accp[pr]));
            int grow = n0 + rb + pr * 2;
            if (grow < NN) {
                float yv = __uint_as_float(lo) + ob;
                y[(size_t)grow * DD + col] = yv;
                ps += yv; pss += yv * yv;
            }
            if (grow + 1 < NN) {
                float yv = __uint_as_float(hi) + ob;
                y[(size_t)(grow + 1) * DD + col] = yv;
                ps += yv; pss += yv * yv;
            }
        }
        sred[0][rg][col] = ps;
        sred[1][rg][col] = pss;
        __syncthreads();
        if (rg == 0) {
            float s = 0.f, ss = 0.f;
            #pragma unroll
            for (int r = 0; r < 8; r++) {
                s  += sred[0][r][col];
                ss += sred[1][r][col];
            }
            atomicAdd(&g_stats[col], s);
            atomicAdd(&g_stats[64 + col], ss);
        }
    }
}

// ---------------- BN finalize / apply ----------------
__global__ void k_bn_fin(const float* __restrict__ g, const float* __restrict__ bt) {
    int c = threadIdx.x;
    float mu  = g_stats[c] * (1.0f / NN);
    float var = g_stats[64 + c] * (1.0f / NN) - mu * mu;
    float sc  = g[c] * rsqrtf(var + EPSBN);
    g_bn[c] = sc;
    g_bn[64 + c] = bt[c] - mu * sc;
}

__global__ void k_bn_relu_out(const float* __restrict__ y, float* __restrict__ out) {
    int i = blockIdx.x * blockDim.x + threadIdx.x;
    if (i < NN * DD) {
        int c = i & 63;
        out[i] = fmaxf(y[i] * g_bn[c] + g_bn[64 + c], 0.f);
    }
}

// ---------------- launch ----------------
extern "C" void kernel_launch(void* const* d_in, const int* in_sizes, int n_in,
                              void* d_out, int out_size) {
    const float* x   = (const float*)d_in[0];
    const int*   src = (const int*)d_in[1];
    const int*   dst = src + NE;
    const float *W1  = (const float*)d_in[2],  *b1  = (const float*)d_in[3];
    const float *fw1 = (const float*)d_in[4],  *fb1 = (const float*)d_in[5];
    const float *g1  = (const float*)d_in[6],  *bt1 = (const float*)d_in[7];
    const float *W2  = (const float*)d_in[8],  *b2  = (const float*)d_in[9];
    const float *fw2 = (const float*)d_in[10], *fb2 = (const float*)d_in[11];
    const float *g2  = (const float*)d_in[12], *bt2 = (const float*)d_in[13];
    float* out = (float*)d_out;

    float *py1, *py2;
    cudaGetSymbolAddress((void**)&py1, g_y1);
    cudaGetSymbolAddress((void**)&py2, g_y2);

    const int T = 256;
    const int elemBlocks  = (NN * DD + T - 1) / T;
    const int nodeBlocks  = (NN + T - 1) / T;
    const int edgeBlocks  = (NE + T - 1) / T;
    const int fusedBlocks = (NN + BNODES - 1) / BNODES;
    dim3 cB(64, 16);

    // ---- CSR build (once; shared by both layers) ----
    k_zero_deg<<<nodeBlocks, T>>>();
    k_hist<<<edgeBlocks, T>>>(dst);
    k_scan1<<<NCHUNK, CHUNK>>>();
    k_scan2<<<1, 256>>>();
    k_scan3<<<nodeBlocks, T>>>();
    k_scatter<<<edgeBlocks, T>>>(src, dst);

    // ---- layer 1:  y1 = (Â x)(W1@fw1) + bc1 ----
    k_combine<<<1, cB>>>(W1, fw1, b1, fb1);             // also zeroes stats
    k_agg_gemm<<<fusedBlocks, 512>>>(x, py1, 0);
    k_bn_fin<<<1, 64>>>(g1, bt1);

    // ---- layer 2:  y2 = (Â bnrelu(y1))(W2@fw2) + bc2 ----
    k_combine<<<1, cB>>>(W2, fw2, b2, fb2);             // also zeroes stats
    k_agg_gemm<<<fusedBlocks, 512>>>(py1, py2, 2);
    k_bn_fin<<<1, 64>>>(g2, bt2);
    k_bn_relu_out<<<elemBlocks, T>>>(py2, out);
}

// round 8
// speedup vs baseline: 1.0772x; 1.0772x over previous
#include <cuda_runtime.h>

#define NN 100000
#define NE 3200000
#define DD 64
#define EPSBN 1e-5f
#define CHUNK 512
#define NCHUNK ((NN + CHUNK - 1) / CHUNK)   // 196

// ---------------- scratch (no allocations allowed) ----------------
__device__ int   g_deg[NN];
__device__ int   g_off[NN + 1];
__device__ int   g_cursor[NN];
__device__ int   g_csum[256];
__device__ int   g_coff[256];
__device__ float g_dinv[NN];
__device__ int2  g_entries[NE];           // {src, weight-bits}
__device__ float g_agg[(size_t)NN * DD];
__device__ float g_y[(size_t)NN * DD];
__device__ float g_stats[2 * DD];
__device__ float g_bn[2 * DD];
__device__ float g_wc[DD * DD];           // combined W@fw
__device__ float g_bc[DD];                // combined bias

// ---------------- CSR build ----------------
__global__ void k_zero_deg() {
    int i = blockIdx.x * blockDim.x + threadIdx.x;
    if (i < NN) g_deg[i] = 0;
}
__global__ void k_hist(const int* __restrict__ dst) {
    int e = blockIdx.x * blockDim.x + threadIdx.x;
    if (e < NE) atomicAdd(&g_deg[dst[e]], 1);
}
__global__ void k_scan1() {
    __shared__ int sh[CHUNK];
    int c = blockIdx.x, t = threadIdx.x;
    int i = c * CHUNK + t;
    int val = (i < NN) ? g_deg[i] : 0;
    sh[t] = val;
    __syncthreads();
    #pragma unroll
    for (int o = 1; o < CHUNK; o <<= 1) {
        int x = (t >= o) ? sh[t - o] : 0;
        __syncthreads();
        sh[t] += x;
        __syncthreads();
    }
    if (i < NN) g_off[i] = sh[t] - val;
    if (t == CHUNK - 1) g_csum[c] = sh[t];
}
__global__ void k_scan2() {
    __shared__ int sh[256];
    int t = threadIdx.x;
    int val = (t < NCHUNK) ? g_csum[t] : 0;
    sh[t] = val;
    __syncthreads();
    #pragma unroll
    for (int o = 1; o < 256; o <<= 1) {
        int x = (t >= o) ? sh[t - o] : 0;
        __syncthreads();
        sh[t] += x;
        __syncthreads();
    }
    g_coff[t] = sh[t] - val;
}
__global__ void k_scan3() {
    int i = blockIdx.x * blockDim.x + threadIdx.x;
    if (i < NN) {
        int v = g_off[i] + g_coff[i / CHUNK];
        g_off[i] = v;
        g_cursor[i] = v;
        g_dinv[i] = rsqrtf((float)(g_deg[i] + 1));   // +1 self loop
        if (i == 0) g_off[NN] = NE;
    }
}
__global__ void k_scatter(const int* __restrict__ src, const int* __restrict__ dst) {
    int e = blockIdx.x * blockDim.x + threadIdx.x;
    if (e >= NE) return;
    int s = src[e], d = dst[e];
    float w = g_dinv[s] * g_dinv[d];
    int pos = atomicAdd(&g_cursor[d], 1);
    g_entries[pos] = make_int2(s, __float_as_int(w));
}

// ---------------- weight combine: Wc = W@fw, bc = b@fw + fb; zero stats ---
__global__ void k_combine(const float* __restrict__ W, const float* __restrict__ fw,
                          const float* __restrict__ b, const float* __restrict__ fb) {
    int col = threadIdx.x;          // 0..63
    int rb  = threadIdx.y * 4;      // row base, y in 0..15
    float acc[4] = {0.f, 0.f, 0.f, 0.f};
    for (int k = 0; k < DD; k++) {
        float f = fw[k * DD + col];
        #pragma unroll
        for (int r = 0; r < 4; r++) acc[r] += W[(rb + r) * DD + k] * f;
    }
    #pragma unroll
    for (int r = 0; r < 4; r++) g_wc[(rb + r) * DD + col] = acc[r];
    if (threadIdx.y == 0) {
        float s = fb[col];
        for (int k = 0; k < DD; k++) s += b[k] * fw[k * DD + col];
        g_bc[col] = s;
    }
    if (threadIdx.y == 1) {
        g_stats[col] = 0.f;
        g_stats[64 + col] = 0.f;
    }
}

// ---------------- aggregation: gather over CSR, self loop folded ----------
// mode 0: raw rows; mode 2: row -> relu(row*g_bn + g_bn[64..]) on load
__global__ void __launch_bounds__(256) k_agg(const float* __restrict__ h,
                                             float* __restrict__ agg, int mode) {
    int node = blockIdx.x * 16 + (threadIdx.x >> 4);
    int q = threadIdx.x & 15;
    if (node >= NN) return;

    float4 sc = make_float4(1.f, 1.f, 1.f, 1.f);
    float4 sh = make_float4(0.f, 0.f, 0.f, 0.f);
    if (mode == 2) {
        sc = *reinterpret_cast<const float4*>(&g_bn[q * 4]);
        sh = *reinterpret_cast<const float4*>(&g_bn[64 + q * 4]);
    }

    int beg = g_off[node];
    int end = g_off[node + 1];
    float di = g_dinv[node];
    float ww = di * di;

    float4 a = *reinterpret_cast<const float4*>(h + (size_t)node * DD + q * 4);
    if (mode == 2) {
        a.x = fmaxf(a.x * sc.x + sh.x, 0.f);
        a.y = fmaxf(a.y * sc.y + sh.y, 0.f);
        a.z = fmaxf(a.z * sc.z + sh.z, 0.f);
        a.w = fmaxf(a.w * sc.w + sh.w, 0.f);
    }
    float4 acc = make_float4(ww * a.x, ww * a.y, ww * a.z, ww * a.w);

    int e = beg;
    for (; e + 2 <= end; e += 2) {
        int2 e0 = g_entries[e];
        int2 e1 = g_entries[e + 1];
        float w0 = __int_as_float(e0.y);
        float w1 = __int_as_float(e1.y);
        float4 v0 = *reinterpret_cast<const float4*>(h + (size_t)e0.x * DD + q * 4);
        float4 v1 = *reinterpret_cast<const float4*>(h + (size_t)e1.x * DD + q * 4);
        if (mode == 2) {
            v0.x = fmaxf(v0.x * sc.x + sh.x, 0.f);
            v0.y = fmaxf(v0.y * sc.y + sh.y, 0.f);
            v0.z = fmaxf(v0.z * sc.z + sh.z, 0.f);
            v0.w = fmaxf(v0.w * sc.w + sh.w, 0.f);
            v1.x = fmaxf(v1.x * sc.x + sh.x, 0.f);
            v1.y = fmaxf(v1.y * sc.y + sh.y, 0.f);
            v1.z = fmaxf(v1.z * sc.z + sh.z, 0.f);
            v1.w = fmaxf(v1.w * sc.w + sh.w, 0.f);
        }
        acc.x += w0 * v0.x + w1 * v1.x;
        acc.y += w0 * v0.y + w1 * v1.y;
        acc.z += w0 * v0.z + w1 * v1.z;
        acc.w += w0 * v0.w + w1 * v1.w;
    }
    if (e < end) {
        int2 e0 = g_entries[e];
        float w0 = __int_as_float(e0.y);
        float4 v0 = *reinterpret_cast<const float4*>(h + (size_t)e0.x * DD + q * 4);
        if (mode == 2) {
            v0.x = fmaxf(v0.x * sc.x + sh.x, 0.f);
            v0.y = fmaxf(v0.y * sc.y + sh.y, 0.f);
            v0.z = fmaxf(v0.z * sc.z + sh.z, 0.f);
            v0.w = fmaxf(v0.w * sc.w + sh.w, 0.f);
        }
        acc.x += w0 * v0.x;
        acc.y += w0 * v0.y;
        acc.z += w0 * v0.z;
        acc.w += w0 * v0.w;
    }
    *reinterpret_cast<float4*>(agg + (size_t)node * DD + q * 4) = acc;
}

// ---------------- GEMM: out[N,64] = in[N,64] @ g_wc + g_bc, col stats -----
// inner loop uses packed fp32x2 FMA (FFMA2) — 8 packed accumulators
__global__ void __launch_bounds__(256) k_gemm(const float* __restrict__ in,
                                              float* __restrict__ out) {
    __shared__ float Xt[DD * 68];
    __shared__ float Ws[DD * DD];
    __shared__ float sred[2][4][DD];

    const int col = threadIdx.x;
    const int rg  = threadIdx.y;
    const int tid = rg * 64 + col;
    const int r0  = blockIdx.x * 64;

    #pragma unroll
    for (int it = 0; it < 4; it++) {
        int fi = (tid + it * 256) * 4;
        *reinterpret_cast<float4*>(&Ws[fi]) =
            *reinterpret_cast<const float4*>(&g_wc[fi]);
    }
    #pragma unroll
    for (int it = 0; it < 4; it++) {
        int fi = (tid + it * 256) * 4;
        int r = fi >> 6;
        int c = fi & 63;
        float4 v;
        if (r0 + r < NN)
            v = *reinterpret_cast<const float4*>(&in[(size_t)(r0 + r) * DD + c]);
        else
            v = make_float4(0.f, 0.f, 0.f, 0.f);
        Xt[(c + 0) * 68 + r] = v.x;
        Xt[(c + 1) * 68 + r] = v.y;
        Xt[(c + 2) * 68 + r] = v.z;
        Xt[(c + 3) * 68 + r] = v.w;
    }
    __syncthreads();

    unsigned long long accp[8];
    #pragma unroll
    for (int r = 0; r < 8; r++) accp[r] = 0ull;

    #pragma unroll 4
    for (int k = 0; k < DD; k++) {
        unsigned int wu = __float_as_uint(Ws[k * DD + col]);
        unsigned long long wp;
        asm("mov.b64 %0, {%1, %1};" : "=l"(wp) : "r"(wu));
        const ulonglong2* xp = reinterpret_cast<const ulonglong2*>(&Xt[k * 68 + rg * 16]);
        ulonglong2 a0 = xp[0], a1 = xp[1], a2 = xp[2], a3 = xp[3];
        asm("fma.rn.f32x2 %0, %1, %2, %0;" : "+l"(accp[0]) : "l"(a0.x), "l"(wp));
        asm("fma.rn.f32x2 %0, %1, %2, %0;" : "+l"(accp[1]) : "l"(a0.y), "l"(wp));
        asm("fma.rn.f32x2 %0, %1, %2, %0;" : "+l"(accp[2]) : "l"(a1.x), "l"(wp));
        asm("fma.rn.f32x2 %0, %1, %2, %0;" : "+l"(accp[3]) : "l"(a1.y), "l"(wp));
        asm("fma.rn.f32x2 %0, %1, %2, %0;" : "+l"(accp[4]) : "l"(a2.x), "l"(wp));
        asm("fma.rn.f32x2 %0, %1, %2, %0;" : "+l"(accp[5]) : "l"(a2.y), "l"(wp));
        asm("fma.rn.f32x2 %0, %1, %2, %0;" : "+l"(accp[6]) : "l"(a3.x), "l"(wp));
        asm("fma.rn.f32x2 %0, %1, %2, %0;" : "+l"(accp[7]) : "l"(a3.y), "l"(wp));
    }

    float ob = g_bc[col];
    float ps = 0.f, pss = 0.f;
    #pragma unroll
    for (int pr = 0; pr < 8; pr++) {
        unsigned int lo, hi;
        asm("mov.b64 {%0, %1}, %2;" : "=r"(lo), "=r"(hi) : "l"(accp[pr]));
        float v0 = __uint_as_float(lo), v1 = __uint_as_float(hi);
        int grow = r0 + rg * 16 + pr * 2;
        if (grow < NN) {
            float y = v0 + ob;
            out[(size_t)grow * DD + col] = y;
            ps += y; pss += y * y;
        }
        if (grow + 1 < NN) {
            float y = v1 + ob;
            out[(size_t)(grow + 1) * DD + col] = y;
            ps += y; pss += y * y;
        }
    }
    sred[0][rg][col] = ps;
    sred[1][rg][col] = pss;
    __syncthreads();
    if (rg == 0) {
        float s  = sred[0][0][col] + sred[0][1][col] + sred[0][2][col] + sred[0][3][col];
        float ss = sred[1][0][col] + sred[1][1][col] + sred[1][2][col] + sred[1][3][col];
        atomicAdd(&g_stats[col], s);
        atomicAdd(&g_stats[64 + col], ss);
    }
}

// ---------------- BN finalize / apply ----------------
__global__ void k_bn_fin(const float* __restrict__ g, const float* __restrict__ bt) {
    int c = threadIdx.x;
    float mu  = g_stats[c] * (1.0f / NN);
    float var = g_stats[64 + c] * (1.0f / NN) - mu * mu;
    float sc  = g[c] * rsqrtf(var + EPSBN);
    g_bn[c] = sc;
    g_bn[64 + c] = bt[c] - mu * sc;
}

__global__ void k_bn_relu_out(const float* __restrict__ y, float* __restrict__ out) {
    int i = blockIdx.x * blockDim.x + threadIdx.x;
    if (i < NN * DD) {
        int c = i & 63;
        out[i] = fmaxf(y[i] * g_bn[c] + g_bn[64 + c], 0.f);
    }
}

// ---------------- launch ----------------
extern "C" void kernel_launch(void* const* d_in, const int* in_sizes, int n_in,
                              void* d_out, int out_size) {
    const float* x   = (const float*)d_in[0];
    const int*   src = (const int*)d_in[1];
    const int*   dst = src + NE;
    const float *W1  = (const float*)d_in[2],  *b1  = (const float*)d_in[3];
    const float *fw1 = (const float*)d_in[4],  *fb1 = (const float*)d_in[5];
    const float *g1  = (const float*)d_in[6],  *bt1 = (const float*)d_in[7];
    const float *W2  = (const float*)d_in[8],  *b2  = (const float*)d_in[9];
    const float *fw2 = (const float*)d_in[10], *fb2 = (const float*)d_in[11];
    const float *g2  = (const float*)d_in[12], *bt2 = (const float*)d_in[13];
    float* out = (float*)d_out;

    float *pagg, *py;
    cudaGetSymbolAddress((void**)&pagg, g_agg);
    cudaGetSymbolAddress((void**)&py,   g_y);

    const int T = 256;
    const int elemBlocks = (NN * DD + T - 1) / T;
    const int nodeBlocks = (NN + T - 1) / T;
    const int edgeBlocks = (NE + T - 1) / T;
    const int gemmBlocks = (NN + 63) / 64;
    const int aggBlocks  = (NN + 15) / 16;
    dim3 gB(64, 4);
    dim3 cB(64, 16);

    // ---- CSR build (once; shared by both layers) ----
    k_zero_deg<<<nodeBlocks, T>>>();
    k_hist<<<edgeBlocks, T>>>(dst);
    k_scan1<<<NCHUNK, CHUNK>>>();
    k_scan2<<<1, 256>>>();
    k_scan3<<<nodeBlocks, T>>>();
    k_scatter<<<edgeBlocks, T>>>(src, dst);

    // ---- layer 1:  y1 = (Â x)(W1@fw1) + bc1 ----
    k_combine<<<1, cB>>>(W1, fw1, b1, fb1);       // also zeroes stats
    k_agg<<<aggBlocks, T>>>(x, pagg, 0);
    k_gemm<<<gemmBlocks, gB>>>(pagg, py);
    k_bn_fin<<<1, 64>>>(g1, bt1);

    // ---- layer 2:  y2 = (Â bnrelu(y1))(W2@fw2) + bc2 ----
    k_combine<<<1, cB>>>(W2, fw2, b2, fb2);       // also zeroes stats
    k_agg<<<aggBlocks, T>>>(py, pagg, 2);
    k_gemm<<<gemmBlocks, gB>>>(pagg, py);
    k_bn_fin<<<1, 64>>>(g2, bt2);
    k_bn_relu_out<<<elemBlocks, T>>>(py, out);
}

// round 9
// speedup vs baseline: 1.1368x; 1.0553x over previous
#include <cuda_runtime.h>
#include <cuda_fp16.h>

#define NN 100000
#define NE 3200000
#define DD 64
#define EPSBN 1e-5f
#define CHUNK 512
#define NCHUNK ((NN + CHUNK - 1) / CHUNK)   // 196

// ---------------- scratch (no allocations allowed) ----------------
__device__ int    g_deg[NN];
__device__ int    g_off[NN + 1];
__device__ int    g_cursor[NN];
__device__ int    g_csum[256];
__device__ int    g_coff[256];
__device__ float  g_dinv[NN];
__device__ int2   g_entries[NE];           // {src, weight-bits}
__device__ __half g_hsrc[(size_t)NN * DD]; // half gather source (x, then y1)
__device__ float  g_agg[(size_t)NN * DD];
__device__ float  g_y[(size_t)NN * DD];
__device__ float  g_stats[2 * DD];
__device__ float  g_bn[2 * DD];
__device__ float  g_wc[DD * DD];           // combined W@fw
__device__ float  g_bc[DD];                // combined bias

// ---------------- CSR build ----------------
__global__ void k_zero_deg() {
    int i = blockIdx.x * blockDim.x + threadIdx.x;
    if (i < NN) g_deg[i] = 0;
}
__global__ void k_hist(const int* __restrict__ dst) {
    int e = blockIdx.x * blockDim.x + threadIdx.x;
    if (e < NE) atomicAdd(&g_deg[dst[e]], 1);
}
__global__ void k_scan1() {
    __shared__ int sh[CHUNK];
    int c = blockIdx.x, t = threadIdx.x;
    int i = c * CHUNK + t;
    int val = (i < NN) ? g_deg[i] : 0;
    sh[t] = val;
    __syncthreads();
    #pragma unroll
    for (int o = 1; o < CHUNK; o <<= 1) {
        int x = (t >= o) ? sh[t - o] : 0;
        __syncthreads();
        sh[t] += x;
        __syncthreads();
    }
    if (i < NN) g_off[i] = sh[t] - val;
    if (t == CHUNK - 1) g_csum[c] = sh[t];
}
__global__ void k_scan2() {
    __shared__ int sh[256];
    int t = threadIdx.x;
    int val = (t < NCHUNK) ? g_csum[t] : 0;
    sh[t] = val;
    __syncthreads();
    #pragma unroll
    for (int o = 1; o < 256; o <<= 1) {
        int x = (t >= o) ? sh[t - o] : 0;
        __syncthreads();
        sh[t] += x;
        __syncthreads();
    }
    g_coff[t] = sh[t] - val;
}
__global__ void k_scan3() {
    int i = blockIdx.x * blockDim.x + threadIdx.x;
    if (i < NN) {
        int v = g_off[i] + g_coff[i / CHUNK];
        g_off[i] = v;
        g_cursor[i] = v;
        g_dinv[i] = rsqrtf((float)(g_deg[i] + 1));   // +1 self loop
        if (i == 0) g_off[NN] = NE;
    }
}
__global__ void k_scatter(const int* __restrict__ src, const int* __restrict__ dst) {
    int e = blockIdx.x * blockDim.x + threadIdx.x;
    if (e >= NE) return;
    int s = src[e], d = dst[e];
    float w = g_dinv[s] * g_dinv[d];
    int pos = atomicAdd(&g_cursor[d], 1);
    g_entries[pos] = make_int2(s, __float_as_int(w));
}

// ---------------- x -> half conversion ----------------
__global__ void k_x2h(const float* __restrict__ x) {
    int i = blockIdx.x * blockDim.x + threadIdx.x;
    if (i < NN * DD / 4) {
        float4 v = reinterpret_cast<const float4*>(x)[i];
        __half2* o = reinterpret_cast<__half2*>(g_hsrc) + 2 * i;
        o[0] = __floats2half2_rn(v.x, v.y);
        o[1] = __floats2half2_rn(v.z, v.w);
    }
}

// ---------------- weight combine: Wc = W@fw, bc = b@fw + fb; zero stats ---
__global__ void k_combine(const float* __restrict__ W, const float* __restrict__ fw,
                          const float* __restrict__ b, const float* __restrict__ fb) {
    int col = threadIdx.x;          // 0..63
    int rb  = threadIdx.y * 4;      // row base, y in 0..15
    float acc[4] = {0.f, 0.f, 0.f, 0.f};
    for (int k = 0; k < DD; k++) {
        float f = fw[k * DD + col];
        #pragma unroll
        for (int r = 0; r < 4; r++) acc[r] += W[(rb + r) * DD + k] * f;
    }
    #pragma unroll
    for (int r = 0; r < 4; r++) g_wc[(rb + r) * DD + col] = acc[r];
    if (threadIdx.y == 0) {
        float s = fb[col];
        for (int k = 0; k < DD; k++) s += b[k] * fw[k * DD + col];
        g_bc[col] = s;
    }
    if (threadIdx.y == 1) {
        g_stats[col] = 0.f;
        g_stats[64 + col] = 0.f;
    }
}

// ---------------- half4 -> float4 helper ----------------
__device__ __forceinline__ float4 h4f(uint2 r) {
    __half2 h0 = *reinterpret_cast<__half2*>(&r.x);
    __half2 h1 = *reinterpret_cast<__half2*>(&r.y);
    float2 f0 = __half22float2(h0);
    float2 f1 = __half22float2(h1);
    return make_float4(f0.x, f0.y, f1.x, f1.y);
}

// ---------------- aggregation: gather over CSR (half rows) ----------------
// mode 0: raw rows; mode 2: row -> relu(row*g_bn + g_bn[64..]) on load
__global__ void __launch_bounds__(256) k_agg(float* __restrict__ agg, int mode) {
    int node = blockIdx.x * 16 + (threadIdx.x >> 4);
    int q = threadIdx.x & 15;                 // 8-byte (4-half) slice index
    if (node >= NN) return;

    float4 sc = make_float4(1.f, 1.f, 1.f, 1.f);
    float4 sh = make_float4(0.f, 0.f, 0.f, 0.f);
    if (mode == 2) {
        sc = *reinterpret_cast<const float4*>(&g_bn[q * 4]);
        sh = *reinterpret_cast<const float4*>(&g_bn[64 + q * 4]);
    }

    int beg = g_off[node];
    int end = g_off[node + 1];
    float di = g_dinv[node];
    float ww = di * di;

    const uint2* hs = reinterpret_cast<const uint2*>(g_hsrc);

    float4 a = h4f(hs[(size_t)node * 16 + q]);
    if (mode == 2) {
        a.x = fmaxf(a.x * sc.x + sh.x, 0.f);
        a.y = fmaxf(a.y * sc.y + sh.y, 0.f);
        a.z = fmaxf(a.z * sc.z + sh.z, 0.f);
        a.w = fmaxf(a.w * sc.w + sh.w, 0.f);
    }
    float4 acc = make_float4(ww * a.x, ww * a.y, ww * a.z, ww * a.w);

    int e = beg;
    for (; e + 2 <= end; e += 2) {
        int2 e0 = g_entries[e];
        int2 e1 = g_entries[e + 1];
        float w0 = __int_as_float(e0.y);
        float w1 = __int_as_float(e1.y);
        float4 v0 = h4f(hs[(size_t)e0.x * 16 + q]);
        float4 v1 = h4f(hs[(size_t)e1.x * 16 + q]);
        if (mode == 2) {
            v0.x = fmaxf(v0.x * sc.x + sh.x, 0.f);
            v0.y = fmaxf(v0.y * sc.y + sh.y, 0.f);
            v0.z = fmaxf(v0.z * sc.z + sh.z, 0.f);
            v0.w = fmaxf(v0.w * sc.w + sh.w, 0.f);
            v1.x = fmaxf(v1.x * sc.x + sh.x, 0.f);
            v1.y = fmaxf(v1.y * sc.y + sh.y, 0.f);
            v1.z = fmaxf(v1.z * sc.z + sh.z, 0.f);
            v1.w = fmaxf(v1.w * sc.w + sh.w, 0.f);
        }
        acc.x += w0 * v0.x + w1 * v1.x;
        acc.y += w0 * v0.y + w1 * v1.y;
        acc.z += w0 * v0.z + w1 * v1.z;
        acc.w += w0 * v0.w + w1 * v1.w;
    }
    if (e < end) {
        int2 e0 = g_entries[e];
        float w0 = __int_as_float(e0.y);
        float4 v0 = h4f(hs[(size_t)e0.x * 16 + q]);
        if (mode == 2) {
            v0.x = fmaxf(v0.x * sc.x + sh.x, 0.f);
            v0.y = fmaxf(v0.y * sc.y + sh.y, 0.f);
            v0.z = fmaxf(v0.z * sc.z + sh.z, 0.f);
            v0.w = fmaxf(v0.w * sc.w + sh.w, 0.f);
        }
        acc.x += w0 * v0.x;
        acc.y += w0 * v0.y;
        acc.z += w0 * v0.z;
        acc.w += w0 * v0.w;
    }
    *reinterpret_cast<float4*>(agg + (size_t)node * DD + q * 4) = acc;
}

// ---------------- GEMM: in[N,64] @ g_wc + g_bc -> out (fp32 or half) ------
// outh != nullptr: write half into g_hsrc-style buffer; else fp32 into out.
__global__ void __launch_bounds__(256) k_gemm(const float* __restrict__ in,
                                              float* __restrict__ out,
                                              __half* __restrict__ outh) {
    __shared__ float Xt[DD * 68];
    __shared__ float Ws[DD * DD];
    __shared__ float sred[2][4][DD];

    const int col = threadIdx.x;
    const int rg  = threadIdx.y;
    const int tid = rg * 64 + col;
    const int r0  = blockIdx.x * 64;

    #pragma unroll
    for (int it = 0; it < 4; it++) {
        int fi = (tid + it * 256) * 4;
        *reinterpret_cast<float4*>(&Ws[fi]) =
            *reinterpret_cast<const float4*>(&g_wc[fi]);
    }
    #pragma unroll
    for (int it = 0; it < 4; it++) {
        int fi = (tid + it * 256) * 4;
        int r = fi >> 6;
        int c = fi & 63;
        float4 v;
        if (r0 + r < NN)
            v = *reinterpret_cast<const float4*>(&in[(size_t)(r0 + r) * DD + c]);
        else
            v = make_float4(0.f, 0.f, 0.f, 0.f);
        Xt[(c + 0) * 68 + r] = v.x;
        Xt[(c + 1) * 68 + r] = v.y;
        Xt[(c + 2) * 68 + r] = v.z;
        Xt[(c + 3) * 68 + r] = v.w;
    }
    __syncthreads();

    unsigned long long accp[8];
    #pragma unroll
    for (int r = 0; r < 8; r++) accp[r] = 0ull;

    #pragma unroll 4
    for (int k = 0; k < DD; k++) {
        unsigned int wu = __float_as_uint(Ws[k * DD + col]);
        unsigned long long wp;
        asm("mov.b64 %0, {%1, %1};" : "=l"(wp) : "r"(wu));
        const ulonglong2* xp = reinterpret_cast<const ulonglong2*>(&Xt[k * 68 + rg * 16]);
        ulonglong2 a0 = xp[0], a1 = xp[1], a2 = xp[2], a3 = xp[3];
        asm("fma.rn.f32x2 %0, %1, %2, %0;" : "+l"(accp[0]) : "l"(a0.x), "l"(wp));
        asm("fma.rn.f32x2 %0, %1, %2, %0;" : "+l"(accp[1]) : "l"(a0.y), "l"(wp));
        asm("fma.rn.f32x2 %0, %1, %2, %0;" : "+l"(accp[2]) : "l"(a1.x), "l"(wp));
        asm("fma.rn.f32x2 %0, %1, %2, %0;" : "+l"(accp[3]) : "l"(a1.y), "l"(wp));
        asm("fma.rn.f32x2 %0, %1, %2, %0;" : "+l"(accp[4]) : "l"(a2.x), "l"(wp));
        asm("fma.rn.f32x2 %0, %1, %2, %0;" : "+l"(accp[5]) : "l"(a2.y), "l"(wp));
        asm("fma.rn.f32x2 %0, %1, %2, %0;" : "+l"(accp[6]) : "l"(a3.x), "l"(wp));
        asm("fma.rn.f32x2 %0, %1, %2, %0;" : "+l"(accp[7]) : "l"(a3.y), "l"(wp));
    }

    float ob = g_bc[col];
    float ps = 0.f, pss = 0.f;
    #pragma unroll
    for (int pr = 0; pr < 8; pr++) {
        unsigned int lo, hi;
        asm("mov.b64 {%0, %1}, %2;" : "=r"(lo), "=r"(hi) : "l"(accp[pr]));
        float v0 = __uint_as_float(lo), v1 = __uint_as_float(hi);
        int grow = r0 + rg * 16 + pr * 2;
        if (grow < NN) {
            float y = v0 + ob;
            if (outh) outh[(size_t)grow * DD + col] = __float2half(y);
            else      out[(size_t)grow * DD + col] = y;
            ps += y; pss += y * y;
        }
        if (grow + 1 < NN) {
            float y = v1 + ob;
            if (outh) outh[(size_t)(grow + 1) * DD + col] = __float2half(y);
            else      out[(size_t)(grow + 1) * DD + col] = y;
            ps += y; pss += y * y;
        }
    }
    sred[0][rg][col] = ps;
    sred[1][rg][col] = pss;
    __syncthreads();
    if (rg == 0) {
        float s  = sred[0][0][col] + sred[0][1][col] + sred[0][2][col] + sred[0][3][col];
        float ss = sred[1][0][col] + sred[1][1][col] + sred[1][2][col] + sred[1][3][col];
        atomicAdd(&g_stats[col], s);
        atomicAdd(&g_stats[64 + col], ss);
    }
}

// ---------------- BN finalize / apply ----------------
__global__ void k_bn_fin(const float* __restrict__ g, const float* __restrict__ bt) {
    int c = threadIdx.x;
    float mu  = g_stats[c] * (1.0f / NN);
    float var = g_stats[64 + c] * (1.0f / NN) - mu * mu;
    float sc  = g[c] * rsqrtf(var + EPSBN);
    g_bn[c] = sc;
    g_bn[64 + c] = bt[c] - mu * sc;
}

__global__ void k_bn_relu_out(const float* __restrict__ y, float* __restrict__ out) {
    int i = blockIdx.x * blockDim.x + threadIdx.x;
    if (i < NN * DD) {
        int c = i & 63;
        out[i] = fmaxf(y[i] * g_bn[c] + g_bn[64 + c], 0.f);
    }
}

// ---------------- launch ----------------
extern "C" void kernel_launch(void* const* d_in, const int* in_sizes, int n_in,
                              void* d_out, int out_size) {
    const float* x   = (const float*)d_in[0];
    const int*   src = (const int*)d_in[1];
    const int*   dst = src + NE;
    const float *W1  = (const float*)d_in[2],  *b1  = (const float*)d_in[3];
    const float *fw1 = (const float*)d_in[4],  *fb1 = (const float*)d_in[5];
    const float *g1  = (const float*)d_in[6],  *bt1 = (const float*)d_in[7];
    const float *W2  = (const float*)d_in[8],  *b2  = (const float*)d_in[9];
    const float *fw2 = (const float*)d_in[10], *fb2 = (const float*)d_in[11];
    const float *g2  = (const float*)d_in[12], *bt2 = (const float*)d_in[13];
    float* out = (float*)d_out;

    float *pagg, *py;
    __half* ph;
    cudaGetSymbolAddress((void**)&pagg, g_agg);
    cudaGetSymbolAddress((void**)&py,   g_y);
    cudaGetSymbolAddress((void**)&ph,   g_hsrc);

    const int T = 256;
    const int elemBlocks = (NN * DD + T - 1) / T;
    const int vecBlocks  = (NN * DD / 4 + T - 1) / T;
    const int nodeBlocks = (NN + T - 1) / T;
    const int edgeBlocks = (NE + T - 1) / T;
    const int gemmBlocks = (NN + 63) / 64;
    const int aggBlocks  = (NN + 15) / 16;
    dim3 gB(64, 4);
    dim3 cB(64, 16);

    // ---- CSR build (once; shared by both layers) + x->half ----
    k_x2h<<<vecBlocks, T>>>(x);
    k_zero_deg<<<nodeBlocks, T>>>();
    k_hist<<<edgeBlocks, T>>>(dst);
    k_scan1<<<NCHUNK, CHUNK>>>();
    k_scan2<<<1, 256>>>();
    k_scan3<<<nodeBlocks, T>>>();
    k_scatter<<<edgeBlocks, T>>>(src, dst);

    // ---- layer 1:  y1 = (Â x)(W1@fw1) + bc1, stored half ----
    k_combine<<<1, cB>>>(W1, fw1, b1, fb1);       // also zeroes stats
    k_agg<<<aggBlocks, T>>>(pagg, 0);             // reads g_hsrc (=half x)
    k_gemm<<<gemmBlocks, gB>>>(pagg, nullptr, ph);// y1 -> half into g_hsrc
    k_bn_fin<<<1, 64>>>(g1, bt1);

    // ---- layer 2:  y2 = (Â bnrelu(y1))(W2@fw2) + bc2 ----
    k_combine<<<1, cB>>>(W2, fw2, b2, fb2);       // also zeroes stats
    k_agg<<<aggBlocks, T>>>(pagg, 2);             // reads g_hsrc (=half y1), bnrelu on load
    k_gemm<<<gemmBlocks, gB>>>(pagg, py, nullptr);
    k_bn_fin<<<1, 64>>>(g2, bt2);
    k_bn_relu_out<<<elemBlocks, T>>>(py, out);
}